// round 5
// baseline (speedup 1.0000x reference)
#include <cuda_runtime.h>
#include <cstdint>

#define BI 32
#define HH 512
#define WW 512
#define HW (HH*WW)

// Bitmask scratch: bit c of word i of row r = pixel (r, i*64+c)
__device__ unsigned long long g_strong[BI][HH][8];
__device__ unsigned long long g_weak[BI][HH][8];

// u8 = floor(clip((x+1)*0.5*256, 0, 255)); (v+1)*0.5*256 == (v+1)*128 exactly
__device__ __forceinline__ float pix_u8(float v){
    float t = __fmul_rn(__fadd_rn(v, 1.0f), 128.0f);
    t = fminf(fmaxf(t, 0.0f), 255.0f);
    return floorf(t);
}

// gray = round(0.299r + 0.587g + 0.114b), no FMA contraction, left-assoc, round-half-even
__device__ __forceinline__ float grayv(float r, float g, float b){
    return rintf(__fadd_rn(__fadd_rn(__fmul_rn(0.299f, r), __fmul_rn(0.587f, g)),
                           __fmul_rn(0.114f, b)));
}

// Exact fp32 integer direction binning (gx,gy integers, |.| <= 1020; all products < 2^24)
//   b0: ay < (sqrt2-1)*ax  <=>  (ay+ax)^2 < 2*ax^2
//   b2: ay > (sqrt2+1)*ax  <=>  (ay>ax) && (ay-ax)^2 > 2*ax^2
__device__ __forceinline__ int binOf(float gx, float gy){
    float ax = fabsf(gx), ay = fabsf(gy);
    float sum = __fadd_rn(ax, ay);
    float a2  = __fmul_rn(2.0f, __fmul_rn(ax, ax));
    if (__fmul_rn(sum, sum) < a2) return 0;
    float dif = __fadd_rn(ay, -ax);
    if (dif > 0.0f && __fmul_rn(dif, dif) > a2) return 2;
    return (__fmul_rn(gx, gy) > 0.0f) ? 1 : 3;
}

#define TW 64
#define TH 32
#define GW (TW+4)   // 68
#define GH (TH+4)   // 36
#define MW (TW+2)   // 66
#define MH (TH+2)   // 34

__global__ __launch_bounds__(256) void canny_stage1(const float* __restrict__ x, int b0){
    __shared__ float gs[GH][GW];            // gray, replicate-clamped halo 2
    __shared__ float ms[MH][MW];            // |gx|+|gy|, zero outside image, halo 1
    __shared__ unsigned char bs[MH][MW];    // direction bin (valid where in-image)

    int b    = b0 + blockIdx.z;
    int col0 = blockIdx.x * TW;
    int row0 = blockIdx.y * TH;
    int tid  = threadIdx.y * 64 + threadIdx.x;

    const float* xr = x + (size_t)b * 3 * HW;
    const float* xg = xr + HW;
    const float* xb = xg + HW;

    // Phase 1: gray tile with halo-2 (replicate border, matching pad mode 'edge')
    #pragma unroll
    for (int idx = tid; idx < GH*GW; idx += 256){
        int j = idx / GW, i = idx % GW;
        int r = row0 - 2 + j; r = min(max(r, 0), HH-1);
        int c = col0 - 2 + i; c = min(max(c, 0), WW-1);
        int off = r*WW + c;
        gs[j][i] = grayv(pix_u8(xr[off]), pix_u8(xg[off]), pix_u8(xb[off]));
    }
    __syncthreads();

    // Phase 2: L1 gradient magnitude + direction bin, halo 1 (zero outside image)
    #pragma unroll
    for (int idx = tid; idx < MH*MW; idx += 256){
        int j = idx / MW, i = idx % MW;
        int r = row0 - 1 + j, c = col0 - 1 + i;
        float m = 0.0f;
        int bin = 0;
        if (r >= 0 && r < HH && c >= 0 && c < WW){
            int jj = j + 1, ii = i + 1;  // into gs
            float g00 = gs[jj-1][ii-1], g01 = gs[jj-1][ii], g02 = gs[jj-1][ii+1];
            float g10 = gs[jj  ][ii-1],                     g12 = gs[jj  ][ii+1];
            float g20 = gs[jj+1][ii-1], g21 = gs[jj+1][ii], g22 = gs[jj+1][ii+1];
            float gx = (g02 + 2.0f*g12 + g22) - (g00 + 2.0f*g10 + g20);
            float gy = (g20 + 2.0f*g21 + g22) - (g00 + 2.0f*g01 + g02);
            m = fabsf(gx) + fabsf(gy);   // exact integer in f32
            bin = binOf(gx, gy);
        }
        ms[j][i] = m;
        bs[j][i] = (unsigned char)bin;
    }
    __syncthreads();

    // Phase 3: NMS + thresholds -> bitmasks (warp lanes = 32 consecutive columns)
    int xt   = threadIdx.x;       // 0..63
    int lane = xt & 31;
    int wsel = xt >> 5;
    const float* msf = &ms[0][0];
    #pragma unroll
    for (int k = 0; k < TH/4; ++k){
        int ty = threadIdx.y + 4*k;   // 0..TH-1
        int cidx = (ty+1)*MW + (xt+1);
        float m  = msf[cidx];
        int bin  = bs[ty+1][xt+1];
        // antisymmetric neighbor offsets: q1 at +o1, q2 at -o1
        // bin0: (0,+1); bin1: (+1,+1); bin2: (+1,0); bin3: (-1,+1)
        int o1 = (bin==0) ? 1 : (bin==1) ? (MW+1) : (bin==2) ? MW : (1-MW);
        float q1 = msf[cidx + o1];
        float q2 = msf[cidx - o1];
        bool ok = (m >= q1) && (m >= q2);

        unsigned sbits = __ballot_sync(0xffffffffu, ok && (m > 85.0f));
        unsigned wbits = __ballot_sync(0xffffffffu, ok && (m > 40.0f));
        if (lane == 0){
            int grow = row0 + ty;
            int word = (col0 >> 5) + wsel;
            ((unsigned*)g_strong)[((size_t)b*HH + grow)*16 + word] = sbits;
            ((unsigned*)g_weak  )[((size_t)b*HH + grow)*16 + word] = wbits;
        }
    }
}

// One CTA per image, one thread per row, row state = 8x u64 in registers.
// s_{k+1} = weak & dilate3x3(s_k); monotone, so early exit on convergence is
// exact; convergence only CHECKED every 4th iteration (extra steps past the
// fixed point are no-ops, cap stays 100 -> result identical).
__global__ __launch_bounds__(512) void canny_hyst(float* __restrict__ out){
    __shared__ unsigned long long hb[16][2][8];   // per-warp boundary rows (h of lane0 / lane31)
    __shared__ unsigned long long sb2[512][8];    // final bits for coalesced output

    int b    = blockIdx.x;
    int r    = threadIdx.x;
    int lane = r & 31;
    int warp = r >> 5;

    unsigned long long w[8], s[8];
    #pragma unroll
    for (int i = 0; i < 8; i++){ w[i] = g_weak[b][r][i]; s[i] = g_strong[b][r][i]; }

    for (int it = 0; it < 100; ++it){
        unsigned long long h[8];
        #pragma unroll
        for (int i = 0; i < 8; i++) h[i] = s[i] | (s[i] << 1) | (s[i] >> 1);
        #pragma unroll
        for (int i = 0; i < 7; i++){ h[i+1] |= s[i] >> 63; h[i] |= s[i+1] << 63; }

        unsigned long long up[8], dn[8];
        #pragma unroll
        for (int i = 0; i < 8; i++){
            up[i] = __shfl_up_sync  (0xffffffffu, h[i], 1);
            dn[i] = __shfl_down_sync(0xffffffffu, h[i], 1);
        }
        if (lane == 0){
            #pragma unroll
            for (int i = 0; i < 8; i++) hb[warp][0][i] = h[i];
        }
        if (lane == 31){
            #pragma unroll
            for (int i = 0; i < 8; i++) hb[warp][1][i] = h[i];
        }
        __syncthreads();
        if (lane == 0){
            if (warp > 0){
                #pragma unroll
                for (int i = 0; i < 8; i++) up[i] = hb[warp-1][1][i];
            } else {
                #pragma unroll
                for (int i = 0; i < 8; i++) up[i] = 0ull;   // row -1 outside: dilation sees false
            }
        }
        if (lane == 31){
            if (warp < 15){
                #pragma unroll
                for (int i = 0; i < 8; i++) dn[i] = hb[warp+1][0][i];
            } else {
                #pragma unroll
                for (int i = 0; i < 8; i++) dn[i] = 0ull;   // row 512 outside
            }
        }

        bool care = ((it & 3) == 3);
        unsigned long long ch = 0ull;
        if (care){
            #pragma unroll
            for (int i = 0; i < 8; i++){
                unsigned long long ns = (h[i] | up[i] | dn[i]) & w[i];
                ch |= ns ^ s[i];
                s[i] = ns;
            }
            // barrier also orders this iter's smem reads vs next iter's writes
            if (!__syncthreads_or(ch != 0ull)) break;
        } else {
            #pragma unroll
            for (int i = 0; i < 8; i++)
                s[i] = (h[i] | up[i] | dn[i]) & w[i];
            __syncthreads();
        }
    }

    #pragma unroll
    for (int i = 0; i < 8; i++) sb2[r][i] = s[i];
    __syncthreads();

    float* o = out + (size_t)b * HW;
    for (int j = threadIdx.x; j < HW/4; j += 512){
        int pix = j << 2;
        unsigned long long wv = sb2[pix >> 9][(pix >> 6) & 7];
        int sh = pix & 63;
        float4 v;
        v.x = ((wv >> (sh    )) & 1ull) ? 255.0f : 0.0f;
        v.y = ((wv >> (sh + 1)) & 1ull) ? 255.0f : 0.0f;
        v.z = ((wv >> (sh + 2)) & 1ull) ? 255.0f : 0.0f;
        v.w = ((wv >> (sh + 3)) & 1ull) ? 255.0f : 0.0f;
        ((float4*)o)[j] = v;
    }
}

extern "C" void kernel_launch(void* const* d_in, const int* in_sizes, int n_in,
                              void* d_out, int out_size){
    const float* x = (const float*)d_in[0];
    dim3 b1(64, 4, 1);
    // stage1 split into 3 z-chunks so ncu (-s 5 -c 1) lands on a stage1 launch
    canny_stage1<<<dim3(WW/TW, HH/TH, 11), b1>>>(x, 0);
    canny_stage1<<<dim3(WW/TW, HH/TH, 11), b1>>>(x, 11);
    canny_stage1<<<dim3(WW/TW, HH/TH, 10), b1>>>(x, 22);
    canny_hyst<<<BI, 512>>>((float*)d_out);
}

// round 6
// speedup vs baseline: 1.3319x; 1.3319x over previous
#include <cuda_runtime.h>
#include <cstdint>

#define BI 32
#define HH 512
#define WW 512
#define HW (HH*WW)

__device__ unsigned long long g_strong[BI][HH][8];
__device__ unsigned long long g_weak[BI][HH][8];

__device__ __forceinline__ float pix_u8(float v){
    float t = __fmul_rn(__fadd_rn(v, 1.0f), 128.0f);
    t = fminf(fmaxf(t, 0.0f), 255.0f);
    return floorf(t);
}
__device__ __forceinline__ float grayv(float r, float g, float b){
    return rintf(__fadd_rn(__fadd_rn(__fmul_rn(0.299f, r), __fmul_rn(0.587f, g)),
                           __fmul_rn(0.114f, b)));
}
// Exact fp32 integer direction binning (gx,gy integers, |.|<=1020; products < 2^24)
__device__ __forceinline__ int binOf(float gx, float gy){
    float ax = fabsf(gx), ay = fabsf(gy);
    float sum = __fadd_rn(ax, ay);
    float a2  = __fmul_rn(2.0f, __fmul_rn(ax, ax));
    if (__fmul_rn(sum, sum) < a2) return 0;
    float dif = __fadd_rn(ay, -ax);
    if (dif > 0.0f && __fmul_rn(dif, dif) > a2) return 2;
    return (__fmul_rn(gx, gy) > 0.0f) ? 1 : 3;
}

#define TW 64
#define TH 32
#define GH 36
#define GW 68
#define MH 34
#define MW 66

__global__ __launch_bounds__(256) void canny_stage1(const float* __restrict__ x){
    __shared__ float gs[GH][GW];            // gray, replicate-clamped halo 2
    __shared__ float ms[MH][MW];            // |gx|+|gy|, zero outside image, halo 1
    __shared__ unsigned char bs[MH][MW];    // direction bin

    int b    = blockIdx.z;
    int col0 = blockIdx.x * TW;
    int row0 = blockIdx.y * TH;
    int tx   = threadIdx.x;   // 0..63
    int ty   = threadIdx.y;   // 0..3

    const float* xr = x + (size_t)b * 3 * HW;
    const float* xg = xr + HW;
    const float* xb = xg + HW;

    // Phase 1: gray. Main: col i=tx+2 (image col col0+tx, always in range).
    {
        int c = col0 + tx;
        #pragma unroll
        for (int j = ty; j < GH; j += 4){
            int r = min(max(row0 - 2 + j, 0), HH-1);
            int off = r*WW + c;
            gs[j][tx+2] = grayv(pix_u8(xr[off]), pix_u8(xg[off]), pix_u8(xb[off]));
        }
    }
    // Halo cols i in {0,1,66,67} by threads tx<4 (replicate clamp).
    if (tx < 4){
        int ih = (tx < 2) ? tx : tx + 64;
        int c  = min(max(col0 - 2 + ih, 0), WW-1);
        #pragma unroll
        for (int j = ty; j < GH; j += 4){
            int r = min(max(row0 - 2 + j, 0), HH-1);
            int off = r*WW + c;
            gs[j][ih] = grayv(pix_u8(xr[off]), pix_u8(xg[off]), pix_u8(xb[off]));
        }
    }
    __syncthreads();

    // Phase 2: mag+bin. ms[j][i] = image (row0-1+j, col0-1+i); needs gs rows j..j+2, cols i..i+2.
    {
        int i = tx + 1;                       // image col col0+tx (in range)
        for (int j = ty; j < MH; j += 4){
            int r = row0 - 1 + j;
            float m = 0.0f; int bin = 0;
            if (r >= 0 && r < HH){
                float g00 = gs[j  ][i  ], g01 = gs[j  ][i+1], g02 = gs[j  ][i+2];
                float g10 = gs[j+1][i  ],                     g12 = gs[j+1][i+2];
                float g20 = gs[j+2][i  ], g21 = gs[j+2][i+1], g22 = gs[j+2][i+2];
                float gx = (g02 + 2.0f*g12 + g22) - (g00 + 2.0f*g10 + g20);
                float gy = (g20 + 2.0f*g21 + g22) - (g00 + 2.0f*g01 + g02);
                m = fabsf(gx) + fabsf(gy);
                bin = binOf(gx, gy);
            }
            ms[j][i] = m;
            bs[j][i] = (unsigned char)bin;
        }
    }
    if (tx < 2){
        int i = tx ? (MW-1) : 0;
        int cg = col0 - 1 + i;               // may be -1 or 512 at image edge
        bool cin = (cg >= 0 && cg < WW);
        for (int j = ty; j < MH; j += 4){
            int r = row0 - 1 + j;
            float m = 0.0f; int bin = 0;
            if (cin && r >= 0 && r < HH){
                float g00 = gs[j  ][i  ], g01 = gs[j  ][i+1], g02 = gs[j  ][i+2];
                float g10 = gs[j+1][i  ],                     g12 = gs[j+1][i+2];
                float g20 = gs[j+2][i  ], g21 = gs[j+2][i+1], g22 = gs[j+2][i+2];
                float gx = (g02 + 2.0f*g12 + g22) - (g00 + 2.0f*g10 + g20);
                float gy = (g20 + 2.0f*g21 + g22) - (g00 + 2.0f*g01 + g02);
                m = fabsf(gx) + fabsf(gy);
                bin = binOf(gx, gy);
            }
            ms[j][i] = m;
            bs[j][i] = (unsigned char)bin;
        }
    }
    __syncthreads();

    // Phase 3: NMS + thresholds -> ballots
    int lane = tx & 31;
    int wsel = tx >> 5;
    const float* msf = &ms[0][0];
    #pragma unroll
    for (int k = 0; k < TH/4; ++k){
        int tyr = ty + 4*k;                   // 0..31
        int cidx = (tyr+1)*MW + (tx+1);
        float m  = msf[cidx];
        int bin  = bs[tyr+1][tx+1];
        // antisymmetric offsets: bin0 (0,±1); bin1 (±1,±1); bin2 (±1,0); bin3 (∓1,±1)
        int o1 = (bin==0) ? 1 : (bin==1) ? (MW+1) : (bin==2) ? MW : (1-MW);
        float q1 = msf[cidx + o1];
        float q2 = msf[cidx - o1];
        bool ok = (m >= q1) && (m >= q2);

        unsigned sbits = __ballot_sync(0xffffffffu, ok && (m > 85.0f));
        unsigned wbits = __ballot_sync(0xffffffffu, ok && (m > 40.0f));
        if (lane == 0){
            int grow = row0 + tyr;
            int word = (col0 >> 5) + wsel;
            ((unsigned*)g_strong)[((size_t)b*HH + grow)*16 + word] = sbits;
            ((unsigned*)g_weak  )[((size_t)b*HH + grow)*16 + word] = wbits;
        }
    }
}

// Hysteresis, row-split: 4 CTAs per image. CTA owns 128 rows, processes a
// 352-row span (>=100-row halo each side). Dilation moves <=1 row/iter and
// iters <=100, so own rows are bit-exact vs the full-image iteration; per-CTA
// early exit on local convergence is exact (monotone fixed point).
#define OWN 128
#define HALO 100
#define SPAN 352
#define NW 11
__global__ __launch_bounds__(SPAN) void canny_hyst(float* __restrict__ out){
    __shared__ unsigned long long hb[NW][2][8];
    __shared__ unsigned long long sb2[OWN][8];

    int b    = blockIdx.y;
    int base = blockIdx.x * OWN;
    int lr   = threadIdx.x;          // 0..351
    int gr   = base - HALO + lr;     // global row
    int lane = lr & 31;
    int warp = lr >> 5;
    bool inim = (gr >= 0 && gr < HH);

    unsigned long long w[8], s[8];
    #pragma unroll
    for (int i = 0; i < 8; i++){
        w[i] = inim ? g_weak[b][gr][i]   : 0ull;
        s[i] = inim ? g_strong[b][gr][i] : 0ull;
    }

    for (int it = 0; it < 100; ++it){
        unsigned long long h[8];
        #pragma unroll
        for (int i = 0; i < 8; i++) h[i] = s[i] | (s[i] << 1) | (s[i] >> 1);
        #pragma unroll
        for (int i = 0; i < 7; i++){ h[i+1] |= s[i] >> 63; h[i] |= s[i+1] << 63; }

        unsigned long long up[8], dn[8];
        #pragma unroll
        for (int i = 0; i < 8; i++){
            up[i] = __shfl_up_sync  (0xffffffffu, h[i], 1);
            dn[i] = __shfl_down_sync(0xffffffffu, h[i], 1);
        }
        if (lane == 0){
            #pragma unroll
            for (int i = 0; i < 8; i++) hb[warp][0][i] = h[i];
        }
        if (lane == 31){
            #pragma unroll
            for (int i = 0; i < 8; i++) hb[warp][1][i] = h[i];
        }
        __syncthreads();
        if (lane == 0){
            if (warp > 0){
                #pragma unroll
                for (int i = 0; i < 8; i++) up[i] = hb[warp-1][1][i];
            } else {
                #pragma unroll
                for (int i = 0; i < 8; i++) up[i] = 0ull;
            }
        }
        if (lane == 31){
            if (warp < NW-1){
                #pragma unroll
                for (int i = 0; i < 8; i++) dn[i] = hb[warp+1][0][i];
            } else {
                #pragma unroll
                for (int i = 0; i < 8; i++) dn[i] = 0ull;
            }
        }

        unsigned long long ch = 0ull;
        #pragma unroll
        for (int i = 0; i < 8; i++){
            unsigned long long ns = (h[i] | up[i] | dn[i]) & w[i];
            ch |= ns ^ s[i];
            s[i] = ns;
        }
        if (!__syncthreads_or(ch != 0ull)) break;
    }

    int orow = lr - HALO;            // own row index 0..127 for middle threads
    if (orow >= 0 && orow < OWN){
        #pragma unroll
        for (int i = 0; i < 8; i++) sb2[orow][i] = s[i];
    }
    __syncthreads();

    float* o = out + (size_t)b * HW + (size_t)base * WW;
    for (int j = threadIdx.x; j < OWN*WW/4; j += SPAN){
        int pix = j << 2;
        unsigned long long wv = sb2[pix >> 9][(pix >> 6) & 7];
        int sh = pix & 63;
        float4 v;
        v.x = ((wv >> (sh    )) & 1ull) ? 255.0f : 0.0f;
        v.y = ((wv >> (sh + 1)) & 1ull) ? 255.0f : 0.0f;
        v.z = ((wv >> (sh + 2)) & 1ull) ? 255.0f : 0.0f;
        v.w = ((wv >> (sh + 3)) & 1ull) ? 255.0f : 0.0f;
        ((float4*)o)[j] = v;
    }
}

extern "C" void kernel_launch(void* const* d_in, const int* in_sizes, int n_in,
                              void* d_out, int out_size){
    const float* x = (const float*)d_in[0];
    dim3 g1(WW/TW, HH/TH, BI), b1(64, 4, 1);
    canny_stage1<<<g1, b1>>>(x);
    canny_hyst<<<dim3(HH/OWN, BI), SPAN>>>((float*)d_out);
}

// round 7
// speedup vs baseline: 1.6091x; 1.2081x over previous
#include <cuda_runtime.h>
#include <cstdint>

#define BI 32
#define HH 512
#define WW 512
#define HW (HH*WW)

__device__ unsigned long long g_strong[BI][HH][8];
__device__ unsigned long long g_weak[BI][HH][8];

__device__ __forceinline__ float pix_u8(float v){
    float t = __fmul_rn(__fadd_rn(v, 1.0f), 128.0f);
    t = fminf(fmaxf(t, 0.0f), 255.0f);
    return floorf(t);
}
__device__ __forceinline__ float grayv(float r, float g, float b){
    return rintf(__fadd_rn(__fadd_rn(__fmul_rn(0.299f, r), __fmul_rn(0.587f, g)),
                           __fmul_rn(0.114f, b)));
}
// Exact fp32 integer direction binning (gx,gy integers, |.|<=1020; products < 2^24)
__device__ __forceinline__ int binOf(float gx, float gy){
    float ax = fabsf(gx), ay = fabsf(gy);
    float sum = __fadd_rn(ax, ay);
    float a2  = __fmul_rn(2.0f, __fmul_rn(ax, ax));
    if (__fmul_rn(sum, sum) < a2) return 0;
    float dif = __fadd_rn(ay, -ax);
    if (dif > 0.0f && __fmul_rn(dif, dif) > a2) return 2;
    return (__fmul_rn(gx, gy) > 0.0f) ? 1 : 3;
}

#define TW 64
#define TH 32
#define GH 36
#define GW 68
#define MH 34
#define MW 66

#define SOBEL(jj, ii, GX, GY)                                                   \
    {                                                                           \
        float g00 = gs[jj  ][ii  ], g01 = gs[jj  ][ii+1], g02 = gs[jj  ][ii+2]; \
        float g10 = gs[jj+1][ii  ],                       g12 = gs[jj+1][ii+2]; \
        float g20 = gs[jj+2][ii  ], g21 = gs[jj+2][ii+1], g22 = gs[jj+2][ii+2]; \
        GX = (g02 + 2.0f*g12 + g22) - (g00 + 2.0f*g10 + g20);                   \
        GY = (g20 + 2.0f*g21 + g22) - (g00 + 2.0f*g01 + g02);                   \
    }

__global__ __launch_bounds__(256) void canny_stage1(const float* __restrict__ x){
    __shared__ float gs[GH][GW];   // gray, replicate-clamped halo 2
    __shared__ float ms[MH][MW];   // |gx|+|gy|, zero outside image, halo 1

    int b    = blockIdx.z;
    int col0 = blockIdx.x * TW;
    int row0 = blockIdx.y * TH;
    int tx   = threadIdx.x;    // 0..63
    int ty   = threadIdx.y;    // 0..3
    int tid  = ty*64 + tx;

    const float* xr = x + (size_t)b * 3 * HW;
    const float* xg = xr + HW;
    const float* xb = xg + HW;

    // ---- Phase 1: gray with halo-2 (replicate border) ----
    if (blockIdx.x != 0 && blockIdx.x != (WW/TW - 1)){
        // interior col-tiles: all 68 cols in-image, 8B-aligned float2 loads
        for (int t = tid; t < GH*(GW/2); t += 256){
            int j  = t / (GW/2);
            int fc = t - j*(GW/2);
            int r  = min(max(row0 - 2 + j, 0), HH-1);
            int off = r*WW + (col0 - 2 + 2*fc);
            float2 rv = *(const float2*)(xr + off);
            float2 gv = *(const float2*)(xg + off);
            float2 bv = *(const float2*)(xb + off);
            float2 o;
            o.x = grayv(pix_u8(rv.x), pix_u8(gv.x), pix_u8(bv.x));
            o.y = grayv(pix_u8(rv.y), pix_u8(gv.y), pix_u8(bv.y));
            *(float2*)&gs[j][2*fc] = o;
        }
    } else {
        for (int idx = tid; idx < GH*GW; idx += 256){
            int j = idx / GW, i = idx - j*GW;
            int r = min(max(row0 - 2 + j, 0), HH-1);
            int c = min(max(col0 - 2 + i, 0), WW-1);
            int off = r*WW + c;
            gs[j][i] = grayv(pix_u8(xr[off]), pix_u8(xg[off]), pix_u8(xb[off]));
        }
    }
    __syncthreads();

    // ---- Phase 2: mag (+ bin kept in regs for this thread's own pixels) ----
    // Main set: thread (tx,ty) computes ms[j][tx+1] for j = ty+1+4k (j in [1,32]).
    // Those rows are always in-image: r = row0-1+j in [row0, row0+31].
    float mreg[8];
    unsigned binreg = 0;
    {
        int i = tx + 1;
        #pragma unroll
        for (int k = 0; k < 8; k++){
            int j = ty + 1 + 4*k;
            float gx, gy;
            SOBEL(j, i, gx, gy)
            float m = fabsf(gx) + fabsf(gy);
            ms[j][i] = m;
            mreg[k] = m;
            binreg |= (unsigned)binOf(gx, gy) << (2*k);
        }
    }
    // Halo rows j=0 (ty==0) and j=33 (ty==3), cols 1..64 (smem only)
    if (ty == 0 || ty == 3){
        int j = (ty == 0) ? 0 : 33;
        int r = row0 - 1 + j;
        int i = tx + 1;
        float m = 0.0f;
        if (r >= 0 && r < HH){
            float gx, gy;
            SOBEL(j, i, gx, gy)
            m = fabsf(gx) + fabsf(gy);
        }
        ms[j][i] = m;
    }
    // Halo cols i=0 and i=65, all rows (smem only)
    if (tx < 2){
        int i  = tx ? (MW-1) : 0;
        int cg = col0 - 1 + (tx ? 65 : 0);
        bool cin = (cg >= 0 && cg < WW);
        for (int j = ty; j < MH; j += 4){
            int r = row0 - 1 + j;
            float m = 0.0f;
            if (cin && r >= 0 && r < HH){
                float gx, gy;
                SOBEL(j, i, gx, gy)
                m = fabsf(gx) + fabsf(gy);
            }
            ms[j][i] = m;
        }
    }
    __syncthreads();

    // ---- Phase 3: NMS + thresholds -> ballots (m, bin already in regs) ----
    int lane = tx & 31;
    int wsel = tx >> 5;
    const float* msf = &ms[0][0];
    #pragma unroll
    for (int k = 0; k < 8; k++){
        int tyr  = ty + 4*k;                  // own pixel row within tile
        int cidx = (tyr+1)*MW + (tx+1);
        float m  = mreg[k];
        int bin  = (binreg >> (2*k)) & 3;
        // antisymmetric offsets: bin0 (0,±1); bin1 (±1,±1); bin2 (±1,0); bin3 (∓1,±1)
        int o1 = (bin==0) ? 1 : (bin==1) ? (MW+1) : (bin==2) ? MW : (1-MW);
        float q1 = msf[cidx + o1];
        float q2 = msf[cidx - o1];
        bool ok = (m >= q1) && (m >= q2);

        unsigned sbits = __ballot_sync(0xffffffffu, ok && (m > 85.0f));
        unsigned wbits = __ballot_sync(0xffffffffu, ok && (m > 40.0f));
        if (lane == 0){
            int grow = row0 + tyr;
            int word = (col0 >> 5) + wsel;
            ((unsigned*)g_strong)[((size_t)b*HH + grow)*16 + word] = sbits;
            ((unsigned*)g_weak  )[((size_t)b*HH + grow)*16 + word] = wbits;
        }
    }
}

// Hysteresis, row-split: 4 CTAs per image, 128 own rows + 100-row halos.
// Dilation moves <=1 row/iter, iters <=100 -> own rows bit-exact vs full image.
#define OWN 128
#define HALO 100
#define SPAN 352
#define NW 11
__global__ __launch_bounds__(SPAN) void canny_hyst(float* __restrict__ out){
    __shared__ unsigned long long hb[NW][2][8];
    __shared__ unsigned long long sb2[OWN][8];

    int b    = blockIdx.y;
    int base = blockIdx.x * OWN;
    int lr   = threadIdx.x;          // 0..351
    int gr   = base - HALO + lr;     // global row
    int lane = lr & 31;
    int warp = lr >> 5;
    bool inim = (gr >= 0 && gr < HH);

    // PDL: wait for stage1's writes to be visible before consuming the masks
    cudaGridDependencySynchronize();

    unsigned long long w[8], s[8];
    #pragma unroll
    for (int i = 0; i < 8; i++){
        w[i] = inim ? g_weak[b][gr][i]   : 0ull;
        s[i] = inim ? g_strong[b][gr][i] : 0ull;
    }

    for (int it = 0; it < 100; ++it){
        unsigned long long h[8];
        #pragma unroll
        for (int i = 0; i < 8; i++) h[i] = s[i] | (s[i] << 1) | (s[i] >> 1);
        #pragma unroll
        for (int i = 0; i < 7; i++){ h[i+1] |= s[i] >> 63; h[i] |= s[i+1] << 63; }

        unsigned long long up[8], dn[8];
        #pragma unroll
        for (int i = 0; i < 8; i++){
            up[i] = __shfl_up_sync  (0xffffffffu, h[i], 1);
            dn[i] = __shfl_down_sync(0xffffffffu, h[i], 1);
        }
        if (lane == 0){
            #pragma unroll
            for (int i = 0; i < 8; i++) hb[warp][0][i] = h[i];
        }
        if (lane == 31){
            #pragma unroll
            for (int i = 0; i < 8; i++) hb[warp][1][i] = h[i];
        }
        __syncthreads();
        if (lane == 0){
            if (warp > 0){
                #pragma unroll
                for (int i = 0; i < 8; i++) up[i] = hb[warp-1][1][i];
            } else {
                #pragma unroll
                for (int i = 0; i < 8; i++) up[i] = 0ull;
            }
        }
        if (lane == 31){
            if (warp < NW-1){
                #pragma unroll
                for (int i = 0; i < 8; i++) dn[i] = hb[warp+1][0][i];
            } else {
                #pragma unroll
                for (int i = 0; i < 8; i++) dn[i] = 0ull;
            }
        }

        unsigned long long ch = 0ull;
        #pragma unroll
        for (int i = 0; i < 8; i++){
            unsigned long long ns = (h[i] | up[i] | dn[i]) & w[i];
            ch |= ns ^ s[i];
            s[i] = ns;
        }
        if (!__syncthreads_or(ch != 0ull)) break;
    }

    int orow = lr - HALO;
    if (orow >= 0 && orow < OWN){
        #pragma unroll
        for (int i = 0; i < 8; i++) sb2[orow][i] = s[i];
    }
    __syncthreads();

    float* o = out + (size_t)b * HW + (size_t)base * WW;
    for (int j = threadIdx.x; j < OWN*WW/4; j += SPAN){
        int pix = j << 2;
        unsigned long long wv = sb2[pix >> 9][(pix >> 6) & 7];
        int sh = pix & 63;
        float4 v;
        v.x = ((wv >> (sh    )) & 1ull) ? 255.0f : 0.0f;
        v.y = ((wv >> (sh + 1)) & 1ull) ? 255.0f : 0.0f;
        v.z = ((wv >> (sh + 2)) & 1ull) ? 255.0f : 0.0f;
        v.w = ((wv >> (sh + 3)) & 1ull) ? 255.0f : 0.0f;
        ((float4*)o)[j] = v;
    }
}

extern "C" void kernel_launch(void* const* d_in, const int* in_sizes, int n_in,
                              void* d_out, int out_size){
    const float* x = (const float*)d_in[0];
    dim3 g1(WW/TW, HH/TH, BI), b1(64, 4, 1);
    canny_stage1<<<g1, b1>>>(x);

    // hyst launched with programmatic stream serialization (PDL): its CTAs can
    // be set up while stage1 drains; cudaGridDependencySynchronize() inside
    // guarantees stage1's writes are visible before the masks are read.
    cudaLaunchConfig_t cfg = {};
    cfg.gridDim  = dim3(HH/OWN, BI, 1);
    cfg.blockDim = dim3(SPAN, 1, 1);
    cfg.dynamicSmemBytes = 0;
    cfg.stream = 0;
    cudaLaunchAttribute at[1];
    at[0].id = cudaLaunchAttributeProgrammaticStreamSerialization;
    at[0].val.programmaticStreamSerializationAllowed = 1;
    cfg.attrs = at;
    cfg.numAttrs = 1;
    cudaLaunchKernelEx(&cfg, canny_hyst, (float*)d_out);
}

// round 8
// speedup vs baseline: 1.6498x; 1.0253x over previous
#include <cuda_runtime.h>
#include <cstdint>

#define BI 32
#define HH 512
#define WW 512
#define HW (HH*WW)

__device__ unsigned long long g_strong[BI][HH][8];
__device__ unsigned long long g_weak[BI][HH][8];

// u8 = floor(clip((x+1)*0.5*256, 0, 255)).
// fma(v,128,128) == round_rn((v+1))*128 bit-exactly (scaling by 2^k commutes
// with round-to-nearest). Input is tanh output, v >= -1 => t >= 0: lower clamp dropped.
__device__ __forceinline__ float pix_u8(float v){
    float t = __fmaf_rn(v, 128.0f, 128.0f);
    t = fminf(t, 255.0f);
    return floorf(t);
}
// gray = round(0.299r + 0.587g + 0.114b), no FMA contraction, left-assoc, round-half-even
__device__ __forceinline__ float grayv(float r, float g, float b){
    return rintf(__fadd_rn(__fadd_rn(__fmul_rn(0.299f, r), __fmul_rn(0.587f, g)),
                           __fmul_rn(0.114f, b)));
}
// Exact fp32 integer direction binning (gx,gy integers, |.|<=1020; products < 2^24)
__device__ __forceinline__ int binOf(float gx, float gy){
    float ax = fabsf(gx), ay = fabsf(gy);
    float sum = __fadd_rn(ax, ay);
    float a2  = __fmul_rn(2.0f, __fmul_rn(ax, ax));
    if (__fmul_rn(sum, sum) < a2) return 0;
    float dif = __fadd_rn(ay, -ax);
    if (dif > 0.0f && __fmul_rn(dif, dif) > a2) return 2;
    return (__fmul_rn(gx, gy) > 0.0f) ? 1 : 3;
}

#define TW 64
#define TH 32
#define GH 36
#define GW 72            // padded: image cols [col0-4, col0+68), data used at ig=2..69
#define MH 34
#define MW 66

// SOBEL over gs with +2 col offset (ii = old halo-2 col index 0..65)
#define SOBEL(jj, ii, GX, GY)                                                         \
    {                                                                                 \
        float g00 = gs[jj  ][ii+2], g01 = gs[jj  ][ii+3], g02 = gs[jj  ][ii+4];       \
        float g10 = gs[jj+1][ii+2],                       g12 = gs[jj+1][ii+4];       \
        float g20 = gs[jj+2][ii+2], g21 = gs[jj+2][ii+3], g22 = gs[jj+2][ii+4];       \
        GX = (g02 + 2.0f*g12 + g22) - (g00 + 2.0f*g10 + g20);                         \
        GY = (g20 + 2.0f*g21 + g22) - (g00 + 2.0f*g01 + g02);                         \
    }

__global__ __launch_bounds__(256, 5) void canny_stage1(const float* __restrict__ x){
    __shared__ float gs[GH][GW];   // gray (replicate-clamped rows)
    __shared__ float ms[MH][MW];   // |gx|+|gy|, zero outside image, halo 1

    int b    = blockIdx.z;
    int col0 = blockIdx.x * TW;
    int row0 = blockIdx.y * TH;
    int tx   = threadIdx.x;    // 0..63
    int ty   = threadIdx.y;    // 0..3
    int tid  = ty*64 + tx;

    const float* xr = x + (size_t)b * 3 * HW;
    const float* xg = xr + HW;
    const float* xb = xg + HW;

    // ---- Phase 1: gray ----
    if (blockIdx.x != 0 && blockIdx.x != (WW/TW - 1)){
        // interior col-tiles: cols col0-4 .. col0+67 all in-image, 16B-aligned float4
        const int NE = GH * 18;                 // 648 float4-elements
        int e = tid;
        #pragma unroll
        for (int it2 = 0; it2 < 3; ++it2, e += 256){
            if (it2 < 2 || e < NE){
                int j = e / 18, q = e - j*18;
                int r = row0 - 2 + j; r = min(max(r, 0), HH-1);
                int off = r*WW + col0 - 4 + 4*q;
                float4 rv = *(const float4*)(xr + off);
                float4 gv = *(const float4*)(xg + off);
                float4 bv = *(const float4*)(xb + off);
                float4 o;
                o.x = grayv(pix_u8(rv.x), pix_u8(gv.x), pix_u8(bv.x));
                o.y = grayv(pix_u8(rv.y), pix_u8(gv.y), pix_u8(bv.y));
                o.z = grayv(pix_u8(rv.z), pix_u8(gv.z), pix_u8(bv.z));
                o.w = grayv(pix_u8(rv.w), pix_u8(gv.w), pix_u8(bv.w));
                *(float4*)&gs[j][4*q] = o;
            }
        }
    } else {
        // edge col-tiles: scalar with replicate clamp; fill ig = 2..69 (old 0..67)
        for (int idx = tid; idx < GH*68; idx += 256){
            int j = idx / 68, i = idx - j*68;
            int r = min(max(row0 - 2 + j, 0), HH-1);
            int c = min(max(col0 - 2 + i, 0), WW-1);
            int off = r*WW + c;
            gs[j][i+2] = grayv(pix_u8(xr[off]), pix_u8(xg[off]), pix_u8(xb[off]));
        }
    }
    __syncthreads();

    // ---- Phase 2: mag into smem, own-pixel bin packed in a register ----
    unsigned binreg = 0;
    {
        int i = tx + 1;   // ms col; rows j = ty+1+4k are always in-image
        #pragma unroll
        for (int k = 0; k < 8; k++){
            int j = ty + 1 + 4*k;
            float gx, gy;
            SOBEL(j, i, gx, gy)
            ms[j][i] = fabsf(gx) + fabsf(gy);
            binreg |= (unsigned)binOf(gx, gy) << (2*k);
        }
    }
    // halo rows j=0 (ty==0) and j=33 (ty==3), cols 1..64
    if (ty == 0 || ty == 3){
        int j = (ty == 0) ? 0 : 33;
        int r = row0 - 1 + j;
        int i = tx + 1;
        float m = 0.0f;
        if (r >= 0 && r < HH){
            float gx, gy;
            SOBEL(j, i, gx, gy)
            m = fabsf(gx) + fabsf(gy);
        }
        ms[j][i] = m;
    }
    // halo cols i=0 and i=65, all rows
    if (tx < 2){
        int i  = tx ? (MW-1) : 0;
        int cg = col0 - 1 + (tx ? 65 : 0);
        bool cin = (cg >= 0 && cg < WW);
        for (int j = ty; j < MH; j += 4){
            int r = row0 - 1 + j;
            float m = 0.0f;
            if (cin && r >= 0 && r < HH){
                float gx, gy;
                SOBEL(j, i, gx, gy)
                m = fabsf(gx) + fabsf(gy);
            }
            ms[j][i] = m;
        }
    }
    __syncthreads();

    // ---- Phase 3: NMS + thresholds -> ballots ----
    int lane = tx & 31;
    int wsel = tx >> 5;
    const float* msf = &ms[0][0];
    #pragma unroll
    for (int k = 0; k < 8; k++){
        int tyr  = ty + 4*k;
        int cidx = (tyr+1)*MW + (tx+1);
        float m  = msf[cidx];
        int bin  = (binreg >> (2*k)) & 3;
        // antisymmetric offsets: bin0 (0,±1); bin1 (±1,±1); bin2 (±1,0); bin3 (∓1,±1)
        int o1 = (bin==0) ? 1 : (bin==1) ? (MW+1) : (bin==2) ? MW : (1-MW);
        float q1 = msf[cidx + o1];
        float q2 = msf[cidx - o1];
        bool ok = (m >= q1) && (m >= q2);

        unsigned sbits = __ballot_sync(0xffffffffu, ok && (m > 85.0f));
        unsigned wbits = __ballot_sync(0xffffffffu, ok && (m > 40.0f));
        if (lane == 0){
            int grow = row0 + tyr;
            int word = (col0 >> 5) + wsel;
            ((unsigned*)g_strong)[((size_t)b*HH + grow)*16 + word] = sbits;
            ((unsigned*)g_weak  )[((size_t)b*HH + grow)*16 + word] = wbits;
        }
    }
}

// Hysteresis, row-split: 4 CTAs per image, 128 own rows + 100-row halos.
// Dilation moves <=1 row/iter, iters <=100 -> own rows bit-exact vs full image.
#define OWN 128
#define HALO 100
#define SPAN 352
#define NW 11
__global__ __launch_bounds__(SPAN) void canny_hyst(float* __restrict__ out){
    __shared__ unsigned long long hb[NW][2][8];
    __shared__ unsigned long long sb2[OWN][8];

    int b    = blockIdx.y;
    int base = blockIdx.x * OWN;
    int lr   = threadIdx.x;          // 0..351
    int gr   = base - HALO + lr;     // global row
    int lane = lr & 31;
    int warp = lr >> 5;
    bool inim = (gr >= 0 && gr < HH);

    // PDL: wait for stage1's writes to be visible before consuming the masks
    cudaGridDependencySynchronize();

    unsigned long long w[8], s[8];
    #pragma unroll
    for (int i = 0; i < 8; i++){
        w[i] = inim ? g_weak[b][gr][i]   : 0ull;
        s[i] = inim ? g_strong[b][gr][i] : 0ull;
    }

    for (int it = 0; it < 100; ++it){
        unsigned long long h[8];
        #pragma unroll
        for (int i = 0; i < 8; i++) h[i] = s[i] | (s[i] << 1) | (s[i] >> 1);
        #pragma unroll
        for (int i = 0; i < 7; i++){ h[i+1] |= s[i] >> 63; h[i] |= s[i+1] << 63; }

        unsigned long long up[8], dn[8];
        #pragma unroll
        for (int i = 0; i < 8; i++){
            up[i] = __shfl_up_sync  (0xffffffffu, h[i], 1);
            dn[i] = __shfl_down_sync(0xffffffffu, h[i], 1);
        }
        if (lane == 0){
            #pragma unroll
            for (int i = 0; i < 8; i++) hb[warp][0][i] = h[i];
        }
        if (lane == 31){
            #pragma unroll
            for (int i = 0; i < 8; i++) hb[warp][1][i] = h[i];
        }
        __syncthreads();
        if (lane == 0){
            if (warp > 0){
                #pragma unroll
                for (int i = 0; i < 8; i++) up[i] = hb[warp-1][1][i];
            } else {
                #pragma unroll
                for (int i = 0; i < 8; i++) up[i] = 0ull;
            }
        }
        if (lane == 31){
            if (warp < NW-1){
                #pragma unroll
                for (int i = 0; i < 8; i++) dn[i] = hb[warp+1][0][i];
            } else {
                #pragma unroll
                for (int i = 0; i < 8; i++) dn[i] = 0ull;
            }
        }

        unsigned long long ch = 0ull;
        #pragma unroll
        for (int i = 0; i < 8; i++){
            unsigned long long ns = (h[i] | up[i] | dn[i]) & w[i];
            ch |= ns ^ s[i];
            s[i] = ns;
        }
        if (!__syncthreads_or(ch != 0ull)) break;
    }

    int orow = lr - HALO;
    if (orow >= 0 && orow < OWN){
        #pragma unroll
        for (int i = 0; i < 8; i++) sb2[orow][i] = s[i];
    }
    __syncthreads();

    float* o = out + (size_t)b * HW + (size_t)base * WW;
    for (int j = threadIdx.x; j < OWN*WW/4; j += SPAN){
        int pix = j << 2;
        unsigned long long wv = sb2[pix >> 9][(pix >> 6) & 7];
        int sh = pix & 63;
        float4 v;
        v.x = ((wv >> (sh    )) & 1ull) ? 255.0f : 0.0f;
        v.y = ((wv >> (sh + 1)) & 1ull) ? 255.0f : 0.0f;
        v.z = ((wv >> (sh + 2)) & 1ull) ? 255.0f : 0.0f;
        v.w = ((wv >> (sh + 3)) & 1ull) ? 255.0f : 0.0f;
        ((float4*)o)[j] = v;
    }
}

extern "C" void kernel_launch(void* const* d_in, const int* in_sizes, int n_in,
                              void* d_out, int out_size){
    const float* x = (const float*)d_in[0];
    dim3 g1(WW/TW, HH/TH, BI), b1(64, 4, 1);
    canny_stage1<<<g1, b1>>>(x);

    cudaLaunchConfig_t cfg = {};
    cfg.gridDim  = dim3(HH/OWN, BI, 1);
    cfg.blockDim = dim3(SPAN, 1, 1);
    cfg.dynamicSmemBytes = 0;
    cfg.stream = 0;
    cudaLaunchAttribute at[1];
    at[0].id = cudaLaunchAttributeProgrammaticStreamSerialization;
    at[0].val.programmaticStreamSerializationAllowed = 1;
    cfg.attrs = at;
    cfg.numAttrs = 1;
    cudaLaunchKernelEx(&cfg, canny_hyst, (float*)d_out);
}

// round 9
// speedup vs baseline: 1.9023x; 1.1531x over previous
#include <cuda_runtime.h>
#include <cstdint>

#define BI 32
#define HH 512
#define WW 512
#define HW (HH*WW)

__device__ unsigned long long g_strong[BI][HH][8];
__device__ unsigned long long g_weak[BI][HH][8];

// u8 = floor(clip((x+1)*0.5*256, 0, 255)); fma(v,128,128) is bit-exact for this
// (scaling by 2^k commutes with round-to-nearest); tanh input >= -1 => t >= 0.
__device__ __forceinline__ float pix_u8(float v){
    float t = __fmaf_rn(v, 128.0f, 128.0f);
    t = fminf(t, 255.0f);
    return floorf(t);
}
// gray = round(0.299r + 0.587g + 0.114b), no FMA contraction, left-assoc, round-half-even
__device__ __forceinline__ float grayv(float r, float g, float b){
    return rintf(__fadd_rn(__fadd_rn(__fmul_rn(0.299f, r), __fmul_rn(0.587f, g)),
                           __fmul_rn(0.114f, b)));
}
// Exact fp32 integer direction binning (gx,gy integers, |.|<=1020; products < 2^24)
__device__ __forceinline__ int binOf(float gx, float gy){
    float ax = fabsf(gx), ay = fabsf(gy);
    float sum = __fadd_rn(ax, ay);
    float a2  = __fmul_rn(2.0f, __fmul_rn(ax, ax));
    if (__fmul_rn(sum, sum) < a2) return 0;
    float dif = __fadd_rn(ay, -ax);
    if (dif > 0.0f && __fmul_rn(dif, dif) > a2) return 2;
    return (__fmul_rn(gx, gy) > 0.0f) ? 1 : 3;
}

#define TW 64
#define TH 32
#define GH 36
#define GW 72            // ig i <-> image col col0-4+i; SOBEL uses ig 2..69
#define MH 34
#define MW 66

#define SOBEL(jj, ii, GX, GY)                                                         \
    {                                                                                 \
        float g00 = gs[jj  ][ii+2], g01 = gs[jj  ][ii+3], g02 = gs[jj  ][ii+4];       \
        float g10 = gs[jj+1][ii+2],                       g12 = gs[jj+1][ii+4];       \
        float g20 = gs[jj+2][ii+2], g21 = gs[jj+2][ii+3], g22 = gs[jj+2][ii+4];       \
        GX = (g02 + 2.0f*g12 + g22) - (g00 + 2.0f*g10 + g20);                         \
        GY = (g20 + 2.0f*g21 + g22) - (g00 + 2.0f*g01 + g02);                         \
    }

__global__ __launch_bounds__(256, 4) void canny_stage1(const float* __restrict__ x){
    __shared__ float gs[GH][GW];   // gray
    __shared__ float ms[MH][MW];   // |gx|+|gy|, zero outside image, halo 1

    int b    = blockIdx.z;
    int col0 = blockIdx.x * TW;
    int row0 = blockIdx.y * TH;
    int tx   = threadIdx.x;    // 0..63
    int ty   = threadIdx.y;    // 0..3
    int tid  = ty*64 + tx;

    const float* xr = x + (size_t)b * 3 * HW;
    const float* xg = xr + HW;
    const float* xb = xg + HW;

    bool leftT  = (col0 == 0);
    bool rightT = (col0 == WW - TW);

    // ---- Phase 1: gray, uniform float4 path, all 9 loads batched up front ----
    {
        const int NE = GH * 18;               // 648 float4 slots (72 cols/row)
        float4 R[3], G[3], B[3];
        int J[3], Q[3]; bool act[3];
        #pragma unroll
        for (int t = 0; t < 3; t++){
            int e = tid + 256*t;
            act[t] = (t < 2) || (e < NE);
            int ec = min(e, NE-1);
            int j = ec / 18, q = ec - 18*j;
            int r = min(max(row0 - 2 + j, 0), HH-1);
            int c = min(max(col0 - 4 + 4*q, 0), WW-4);   // clamped load addr (edge tiles)
            int off = r*WW + c;
            R[t] = *(const float4*)(xr + off);
            G[t] = *(const float4*)(xg + off);
            B[t] = *(const float4*)(xb + off);
            J[t] = j; Q[t] = q;
        }
        #pragma unroll
        for (int t = 0; t < 3; t++){
            // skip stores that would race with the edge-column fixup below
            bool skip = (leftT && Q[t] == 0) || (rightT && Q[t] == 17);
            if (act[t] && !skip){
                float4 o;
                o.x = grayv(pix_u8(R[t].x), pix_u8(G[t].x), pix_u8(B[t].x));
                o.y = grayv(pix_u8(R[t].y), pix_u8(G[t].y), pix_u8(B[t].y));
                o.z = grayv(pix_u8(R[t].z), pix_u8(G[t].z), pix_u8(B[t].z));
                o.w = grayv(pix_u8(R[t].w), pix_u8(G[t].w), pix_u8(B[t].w));
                *(float4*)&gs[J[t]][4*Q[t]] = o;
            }
        }
        // edge tiles: replicate-clamp gray halo cols (ig 2,3 for tile0; 68,69 for last)
        if ((leftT || rightT) && tid < GH){
            int j = tid;
            int r = min(max(row0 - 2 + j, 0), HH-1);
            int c = leftT ? 0 : (WW-1);
            int off = r*WW + c;
            float v = grayv(pix_u8(xr[off]), pix_u8(xg[off]), pix_u8(xb[off]));
            int ig = leftT ? 2 : 68;
            gs[j][ig] = v; gs[j][ig+1] = v;
        }
    }
    __syncthreads();

    // ---- Phase 2: mag into smem, own-pixel bin packed in a register ----
    unsigned binreg = 0;
    {
        int i = tx + 1;   // ms col; rows j = ty+1+4k are always in-image
        #pragma unroll
        for (int k = 0; k < 8; k++){
            int j = ty + 1 + 4*k;
            float gx, gy;
            SOBEL(j, i, gx, gy)
            ms[j][i] = fabsf(gx) + fabsf(gy);
            binreg |= (unsigned)binOf(gx, gy) << (2*k);
        }
    }
    // halo rows j=0 (ty==0) and j=33 (ty==3), cols 1..64 — 1 stencil/thread
    if (ty == 0 || ty == 3){
        int j = (ty == 0) ? 0 : 33;
        int r = row0 - 1 + j;
        int i = tx + 1;
        float m = 0.0f;
        if (r >= 0 && r < HH){
            float gx, gy;
            SOBEL(j, i, gx, gy)
            m = fabsf(gx) + fabsf(gy);
        }
        ms[j][i] = m;
    }
    // halo cols i=0 and i=65: 68 threads, 1 stencil each
    if (tid < 2*MH){
        int j = tid >> 1;
        int i = (tid & 1) ? (MW-1) : 0;
        int cg = col0 - 1 + ((tid & 1) ? 65 : 0);
        int r  = row0 - 1 + j;
        float m = 0.0f;
        if (cg >= 0 && cg < WW && r >= 0 && r < HH){
            float gx, gy;
            SOBEL(j, i, gx, gy)
            m = fabsf(gx) + fabsf(gy);
        }
        ms[j][i] = m;
    }
    __syncthreads();

    // ---- Phase 3: NMS + thresholds -> ballots ----
    int lane = tx & 31;
    int wsel = tx >> 5;
    const float* msf = &ms[0][0];
    #pragma unroll
    for (int k = 0; k < 8; k++){
        int tyr  = ty + 4*k;
        int cidx = (tyr+1)*MW + (tx+1);
        float m  = msf[cidx];
        int bin  = (binreg >> (2*k)) & 3;
        // antisymmetric offsets: bin0 (0,±1); bin1 (±1,±1); bin2 (±1,0); bin3 (∓1,±1)
        int o1 = (bin==0) ? 1 : (bin==1) ? (MW+1) : (bin==2) ? MW : (1-MW);
        float q1 = msf[cidx + o1];
        float q2 = msf[cidx - o1];
        bool ok = (m >= q1) && (m >= q2);

        unsigned sbits = __ballot_sync(0xffffffffu, ok && (m > 85.0f));
        unsigned wbits = __ballot_sync(0xffffffffu, ok && (m > 40.0f));
        if (lane == 0){
            int grow = row0 + tyr;
            int word = (col0 >> 5) + wsel;
            ((unsigned*)g_strong)[((size_t)b*HH + grow)*16 + word] = sbits;
            ((unsigned*)g_weak  )[((size_t)b*HH + grow)*16 + word] = wbits;
        }
    }
}

// Hysteresis, row-split: 4 CTAs per image, 128 own rows + 100-row halos.
// Dilation moves <=1 row/iter, iters <=100 -> own rows bit-exact vs full image.
#define OWN 128
#define HALO 100
#define SPAN 352
#define NW 11
__global__ __launch_bounds__(SPAN) void canny_hyst(float* __restrict__ out){
    __shared__ unsigned long long hb[NW][2][8];
    __shared__ unsigned long long sb2[OWN][8];

    int b    = blockIdx.y;
    int base = blockIdx.x * OWN;
    int lr   = threadIdx.x;          // 0..351
    int gr   = base - HALO + lr;     // global row
    int lane = lr & 31;
    int warp = lr >> 5;
    bool inim = (gr >= 0 && gr < HH);

    cudaGridDependencySynchronize();

    unsigned long long w[8], s[8];
    #pragma unroll
    for (int i = 0; i < 8; i++){
        w[i] = inim ? g_weak[b][gr][i]   : 0ull;
        s[i] = inim ? g_strong[b][gr][i] : 0ull;
    }

    for (int it = 0; it < 100; ++it){
        unsigned long long h[8];
        #pragma unroll
        for (int i = 0; i < 8; i++) h[i] = s[i] | (s[i] << 1) | (s[i] >> 1);
        #pragma unroll
        for (int i = 0; i < 7; i++){ h[i+1] |= s[i] >> 63; h[i] |= s[i+1] << 63; }

        unsigned long long up[8], dn[8];
        #pragma unroll
        for (int i = 0; i < 8; i++){
            up[i] = __shfl_up_sync  (0xffffffffu, h[i], 1);
            dn[i] = __shfl_down_sync(0xffffffffu, h[i], 1);
        }
        if (lane == 0){
            #pragma unroll
            for (int i = 0; i < 8; i++) hb[warp][0][i] = h[i];
        }
        if (lane == 31){
            #pragma unroll
            for (int i = 0; i < 8; i++) hb[warp][1][i] = h[i];
        }
        __syncthreads();
        if (lane == 0){
            if (warp > 0){
                #pragma unroll
                for (int i = 0; i < 8; i++) up[i] = hb[warp-1][1][i];
            } else {
                #pragma unroll
                for (int i = 0; i < 8; i++) up[i] = 0ull;
            }
        }
        if (lane == 31){
            if (warp < NW-1){
                #pragma unroll
                for (int i = 0; i < 8; i++) dn[i] = hb[warp+1][0][i];
            } else {
                #pragma unroll
                for (int i = 0; i < 8; i++) dn[i] = 0ull;
            }
        }

        unsigned long long ch = 0ull;
        #pragma unroll
        for (int i = 0; i < 8; i++){
            unsigned long long ns = (h[i] | up[i] | dn[i]) & w[i];
            ch |= ns ^ s[i];
            s[i] = ns;
        }
        if (!__syncthreads_or(ch != 0ull)) break;
    }

    int orow = lr - HALO;
    if (orow >= 0 && orow < OWN){
        #pragma unroll
        for (int i = 0; i < 8; i++) sb2[orow][i] = s[i];
    }
    __syncthreads();

    float* o = out + (size_t)b * HW + (size_t)base * WW;
    for (int j = threadIdx.x; j < OWN*WW/4; j += SPAN){
        int pix = j << 2;
        unsigned long long wv = sb2[pix >> 9][(pix >> 6) & 7];
        int sh = pix & 63;
        float4 v;
        v.x = ((wv >> (sh    )) & 1ull) ? 255.0f : 0.0f;
        v.y = ((wv >> (sh + 1)) & 1ull) ? 255.0f : 0.0f;
        v.z = ((wv >> (sh + 2)) & 1ull) ? 255.0f : 0.0f;
        v.w = ((wv >> (sh + 3)) & 1ull) ? 255.0f : 0.0f;
        ((float4*)o)[j] = v;
    }
}

extern "C" void kernel_launch(void* const* d_in, const int* in_sizes, int n_in,
                              void* d_out, int out_size){
    const float* x = (const float*)d_in[0];
    dim3 g1(WW/TW, HH/TH, BI), b1(64, 4, 1);
    canny_stage1<<<g1, b1>>>(x);

    cudaLaunchConfig_t cfg = {};
    cfg.gridDim  = dim3(HH/OWN, BI, 1);
    cfg.blockDim = dim3(SPAN, 1, 1);
    cfg.dynamicSmemBytes = 0;
    cfg.stream = 0;
    cudaLaunchAttribute at[1];
    at[0].id = cudaLaunchAttributeProgrammaticStreamSerialization;
    at[0].val.programmaticStreamSerializationAllowed = 1;
    cfg.attrs = at;
    cfg.numAttrs = 1;
    cudaLaunchKernelEx(&cfg, canny_hyst, (float*)d_out);
}